// round 8
// baseline (speedup 1.0000x reference)
#include <cuda_runtime.h>

typedef unsigned long long u64;

#define BATCH 8
#define DIM   64
#define TLEN  16384
#define INNER 128
#define TT    128
#define NTILES (TLEN/TT)
#define TTO   256
#define NTILES_O (TLEN/TTO)
#define LOG2E 1.4426950408889634f

// Scratch (device globals; no runtime allocation)
__device__ float g_E[(size_t)BATCH*INNER*TLEN];   // 64 MB: exp(qraw)
__device__ float g_qsum[BATCH*INNER];
__device__ float g_ksum[BATCH*INNER];
__device__ float g_xsum[BATCH*DIM];
__device__ float g_A[BATCH*64*INNER];

// ---- packed fp32x2 helpers (Blackwell) ----
__device__ __forceinline__ u64 pack2(float lo, float hi) {
    u64 r; asm("mov.b64 %0, {%1,%2};" : "=l"(r) : "f"(lo), "f"(hi)); return r;
}
__device__ __forceinline__ float2 unpack2(u64 v) {
    float lo, hi; asm("mov.b64 {%0,%1}, %2;" : "=f"(lo), "=f"(hi) : "l"(v));
    return make_float2(lo, hi);
}
__device__ __forceinline__ void fma2(u64 &d, u64 a, u64 b) {
    asm("fma.rn.f32x2 %0, %1, %2, %0;" : "+l"(d) : "l"(a), "l"(b));
}
__device__ __forceinline__ u64 add2(u64 a, u64 b) {
    u64 r; asm("add.rn.f32x2 %0, %1, %2;" : "=l"(r) : "l"(a), "l"(b)); return r;
}
__device__ __forceinline__ float ex2(float x) {
    float r; asm("ex2.approx.f32 %0, %1;" : "=f"(r) : "f"(x)); return r;
}
__device__ __forceinline__ float rcpa(float x) {
    float r; asm("rcp.approx.f32 %0, %1;" : "=f"(r) : "f"(x)); return r;
}

__global__ void k_zero() {
    int i = blockIdx.x*blockDim.x + threadIdx.x;
    if (i < BATCH*INNER) { g_qsum[i] = 0.f; g_ksum[i] = 0.f; }
    if (i < BATCH*DIM)   { g_xsum[i] = 0.f; }
}

// 128(c) x 128(t) tile GEMM. W plain fp32 in smem; dup to f32x2 in regs.
// Thread's 8 t's = {tx*4..+3} and {64+tx*4..+3} (conflict-free LDS.128).
__device__ __forceinline__ void mm_tile2(const float* __restrict__ xs,
                                         const float* __restrict__ ws,
                                         int tx, int ty, u64 acc[8][4]) {
    #pragma unroll 8
    for (int kk = 0; kk < DIM; kk++) {
        ulonglong2 xa = *(const ulonglong2*)&xs[kk*TT + tx*4];
        ulonglong2 xb = *(const ulonglong2*)&xs[kk*TT + 64 + tx*4];
        float4 w0 = *(const float4*)&ws[kk*INNER + ty*8];
        float4 w1 = *(const float4*)&ws[kk*INNER + ty*8 + 4];
        float wf[8] = {w0.x,w0.y,w0.z,w0.w,w1.x,w1.y,w1.z,w1.w};
        #pragma unroll
        for (int j = 0; j < 8; j++) {
            u64 wd = pack2(wf[j], wf[j]);
            fma2(acc[j][0], wd, xa.x);
            fma2(acc[j][1], wd, xa.y);
            fma2(acc[j][2], wd, xb.x);
            fma2(acc[j][3], wd, xb.y);
        }
    }
}

// Pass 1: per (b, t-tile): qraw -> exp2 -> E + qsum ; kraw -> per-t head softmax -> ksum ; xsum
__global__ void __launch_bounds__(256, 3) k_reduce(const float* __restrict__ x,
                                                   const float* __restrict__ wqkv) {
    extern __shared__ float sm[];
    float* ws  = sm;                 // [64][128]  32 KB (transposed, *log2e)
    float* xs  = sm + DIM*INNER;     // [64][TT]   32 KB
    float* red = xs + DIM*TT;        // [16][TT]    8 KB
    const int b   = blockIdx.y;
    const int t0  = blockIdx.x * TT;
    const int tid = threadIdx.x;
    const int tx  = tid & 15;   // t quads at tx*4 and 64+tx*4
    const int ty  = tid >> 4;   // c subtile (8 consecutive c each)

    const float* xb = x + (size_t)b*DIM*TLEN + t0;
    for (int idx = tid; idx < DIM*TT; idx += 256) {
        int kk = idx >> 7, t = idx & (TT-1);
        xs[idx] = xb[(size_t)kk*TLEN + t];
    }
    // Wq transposed, *log2e
    for (int idx = tid; idx < DIM*INNER; idx += 256) {
        int c = idx >> 6, kk = idx & 63;
        ws[kk*INNER + c] = wqkv[idx] * LOG2E;
    }
    __syncthreads();

    if (tid < DIM) {
        float s = 0.f;
        #pragma unroll 8
        for (int t = 0; t < TT; t++) s += xs[tid*TT + t];
        atomicAdd(&g_xsum[b*DIM + tid], s);
    }

    u64 acc[8][4];
    #pragma unroll
    for (int j = 0; j < 8; j++)
        #pragma unroll
        for (int p = 0; p < 4; p++) acc[j][p] = 0ull;

    // ---- Phase A: qraw ----
    mm_tile2(xs, ws, tx, ty, acc);

    #pragma unroll
    for (int j = 0; j < 8; j++) {
        int c = ty*8 + j;
        float e[8]; float s = 0.f;
        #pragma unroll
        for (int p = 0; p < 4; p++) {
            float2 v = unpack2(acc[j][p]);
            e[2*p]   = ex2(v.x);
            e[2*p+1] = ex2(v.y);
            s += e[2*p] + e[2*p+1];
        }
        #pragma unroll
        for (int off = 8; off > 0; off >>= 1)
            s += __shfl_down_sync(0xffffffffu, s, off, 16);
        if (tx == 0) atomicAdd(&g_qsum[b*INNER + c], s);
        float* eb0 = &g_E[((size_t)b*INNER + c)*TLEN + t0];
        *(float4*)&eb0[tx*4]      = make_float4(e[0], e[1], e[2], e[3]);
        *(float4*)&eb0[64 + tx*4] = make_float4(e[4], e[5], e[6], e[7]);
    }
    __syncthreads();   // all Wq reads done

    // Wk transposed, *log2e
    for (int idx = tid; idx < DIM*INNER; idx += 256) {
        int c = idx >> 6, kk = idx & 63;
        ws[kk*INNER + c] = wqkv[INNER*DIM + idx] * LOG2E;
    }
    __syncthreads();

    #pragma unroll
    for (int j = 0; j < 8; j++)
        #pragma unroll
        for (int p = 0; p < 4; p++) acc[j][p] = 0ull;

    // ---- Phase B: kraw ----
    mm_tile2(xs, ws, tx, ty, acc);

    // exp2 + per-t partial sums (packed over t pairs)
    u64 pt2[4] = {0ull, 0ull, 0ull, 0ull};
    #pragma unroll
    for (int j = 0; j < 8; j++)
        #pragma unroll
        for (int p = 0; p < 4; p++) {
            float2 v = unpack2(acc[j][p]);
            u64 e2 = pack2(ex2(v.x), ex2(v.y));
            acc[j][p] = e2;
            pt2[p] = add2(pt2[p], e2);
        }
    // t offsets for p: 0->tx*4, 1->tx*4+2, 2->64+tx*4, 3->64+tx*4+2
    *(u64*)&red[ty*TT + tx*4]          = pt2[0];
    *(u64*)&red[ty*TT + tx*4 + 2]      = pt2[1];
    *(u64*)&red[ty*TT + 64 + tx*4]     = pt2[2];
    *(u64*)&red[ty*TT + 64 + tx*4 + 2] = pt2[3];
    __syncthreads();

    // head sums over d (32 channels = 4 consecutive ty rows) -> 1/hs, then ksum
    const int rb = (ty & ~3)*TT;
    const int toff[4] = {tx*4, tx*4 + 2, 64 + tx*4, 64 + tx*4 + 2};
    u64 inv2[4];
    #pragma unroll
    for (int p = 0; p < 4; p++) {
        int o = rb + toff[p];
        u64 h = add2(add2(*(const u64*)&red[o],
                          *(const u64*)&red[o + TT]),
                     add2(*(const u64*)&red[o + 2*TT],
                          *(const u64*)&red[o + 3*TT]));
        float2 hf = unpack2(h);
        inv2[p] = pack2(rcpa(hf.x), rcpa(hf.y));
    }
    #pragma unroll
    for (int j = 0; j < 8; j++) {
        u64 s2 = 0ull;
        #pragma unroll
        for (int p = 0; p < 4; p++) fma2(s2, acc[j][p], inv2[p]);
        float2 v = unpack2(s2);
        float s = v.x + v.y;
        #pragma unroll
        for (int off = 8; off > 0; off >>= 1)
            s += __shfl_down_sync(0xffffffffu, s, off, 16);
        if (tx == 0) atomicAdd(&g_ksum[b*INNER + ty*8 + j], s);
    }
}

// Pass 2 (tiny): vsum = Wv @ xsum ; A[b][o][c] = w_out[o][c] * ksum*vsum/qsum
__global__ void k_scale(const float* __restrict__ wqkv,
                        const float* __restrict__ wout) {
    int b = blockIdx.x, c = threadIdx.x;   // 128 threads
    __shared__ float ss[INNER];
    float vs = 0.f;
    const float* wv = wqkv + (size_t)(2*INNER + c)*DIM;
    #pragma unroll
    for (int kk = 0; kk < DIM; kk++) vs += wv[kk] * g_xsum[b*DIM + kk];
    ss[c] = g_ksum[b*INNER + c] * vs / g_qsum[b*INNER + c];
    __syncthreads();
    for (int idx = c; idx < 64*INNER; idx += 128) {
        int cc = idx & 127;
        g_A[b*64*INNER + idx] = wout[idx] * ss[cc];
    }
}

// Pass 3: y[b,o,t] = sum_c A[b,o,c] * E[b,c,t] + b_out[o]
// 256t x 64o tile per block, c streamed through smem in 4 quarters of 32.
// Thread: 8t ({tx*4..+3} and {128+tx*4..+3}) x 8o (ty*8..+7). Conflict-free LDS.
__global__ void __launch_bounds__(256, 3) k_out(const float* __restrict__ bout,
                                                float* __restrict__ y) {
    extern __shared__ float sm[];
    float* Es = sm;                      // [32][TTO]  32 KB (one c-quarter)
    float* As = sm + 32*TTO;             // [128][64]  32 KB (c-major, o inner)
    float* bo = As + INNER*64;           // [64]
    const int b   = blockIdx.y;
    const int t0  = blockIdx.x * TTO;
    const int tid = threadIdx.x;
    const int tx  = tid & 31;    // t quads at tx*4 and 128+tx*4
    const int ty  = tid >> 5;    // 8 o each -> 64 o

    for (int idx = tid; idx < 64*INNER; idx += 256) {
        int o = idx >> 7, c = idx & 127;
        As[c*64 + o] = g_A[b*64*INNER + idx];
    }
    if (tid < 64) bo[tid] = bout[tid];

    u64 acc[8][4];
    #pragma unroll
    for (int j = 0; j < 8; j++)
        #pragma unroll
        for (int p = 0; p < 4; p++) acc[j][p] = 0ull;

    #pragma unroll
    for (int h = 0; h < 4; h++) {
        const int c0 = h*32;
        __syncthreads();   // (h=0: also covers As/bo fill) Es free to overwrite
        for (int idx = tid; idx < 32*TTO; idx += 256)
            Es[idx] = g_E[((size_t)b*INNER + c0 + (idx >> 8))*TLEN + t0 + (idx & 255)];
        __syncthreads();

        #pragma unroll 8
        for (int cc = 0; cc < 32; cc++) {
            ulonglong2 ea = *(const ulonglong2*)&Es[cc*TTO + tx*4];
            ulonglong2 eb = *(const ulonglong2*)&Es[cc*TTO + 128 + tx*4];
            float4 a0 = *(const float4*)&As[(c0 + cc)*64 + ty*8];
            float4 a1 = *(const float4*)&As[(c0 + cc)*64 + ty*8 + 4];
            float af[8] = {a0.x,a0.y,a0.z,a0.w,a1.x,a1.y,a1.z,a1.w};
            #pragma unroll
            for (int j = 0; j < 8; j++) {
                u64 ad = pack2(af[j], af[j]);
                fma2(acc[j][0], ad, ea.x);
                fma2(acc[j][1], ad, ea.y);
                fma2(acc[j][2], ad, eb.x);
                fma2(acc[j][3], ad, eb.y);
            }
        }
    }

    #pragma unroll
    for (int j = 0; j < 8; j++) {
        int o = ty*8 + j;
        u64 bb = pack2(bo[o], bo[o]);
        ulonglong2 r0, r1;
        r0.x = add2(acc[j][0], bb); r0.y = add2(acc[j][1], bb);
        r1.x = add2(acc[j][2], bb); r1.y = add2(acc[j][3], bb);
        float* yb = &y[((size_t)b*64 + o)*TLEN + t0];
        *(ulonglong2*)&yb[tx*4]       = r0;
        *(ulonglong2*)&yb[128 + tx*4] = r1;
    }
}

#define SMEM_REDUCE ((DIM*INNER + DIM*TT + 16*TT)*4)   /* 73728 */
#define SMEM_OUT    ((32*TTO + INNER*64 + 64)*4)       /* 65792 */

extern "C" void kernel_launch(void* const* d_in, const int* in_sizes, int n_in,
                              void* d_out, int out_size) {
    const float* x    = (const float*)d_in[0];
    const float* wqkv = (const float*)d_in[1];
    const float* wout = (const float*)d_in[2];
    const float* bout = (const float*)d_in[3];
    float* y = (float*)d_out;

    cudaFuncSetAttribute((const void*)k_reduce,
                         cudaFuncAttributeMaxDynamicSharedMemorySize, SMEM_REDUCE);
    cudaFuncSetAttribute((const void*)k_out,
                         cudaFuncAttributeMaxDynamicSharedMemorySize, SMEM_OUT);

    k_zero<<<4, 256>>>();
    dim3 g(NTILES, BATCH);
    k_reduce<<<g, 256, SMEM_REDUCE>>>(x, wqkv);
    k_scale<<<BATCH, 128>>>(wqkv, wout);
    dim3 go(NTILES_O, BATCH);
    k_out<<<go, 256, SMEM_OUT>>>(bout, y);
}

// round 9
// speedup vs baseline: 1.5038x; 1.5038x over previous
#include <cuda_runtime.h>

typedef unsigned long long u64;

#define BATCH 8
#define DIM   64
#define TLEN  16384
#define INNER 128
#define TT    128
#define NTILES (TLEN/TT)
#define TTO   256
#define NTILES_O (TLEN/TTO)
#define LOG2E 1.4426950408889634f

// Scratch (device globals; no runtime allocation)
__device__ float g_E[(size_t)BATCH*INNER*TLEN];   // 64 MB: exp(qraw)
__device__ float g_qsum[BATCH*INNER];
__device__ float g_ksum[BATCH*INNER];
__device__ float g_xsum[BATCH*DIM];
__device__ float g_A[BATCH*64*INNER];

// ---- packed fp32x2 helpers (Blackwell) ----
__device__ __forceinline__ u64 pack2(float lo, float hi) {
    u64 r; asm("mov.b64 %0, {%1,%2};" : "=l"(r) : "f"(lo), "f"(hi)); return r;
}
__device__ __forceinline__ float2 unpack2(u64 v) {
    float lo, hi; asm("mov.b64 {%0,%1}, %2;" : "=f"(lo), "=f"(hi) : "l"(v));
    return make_float2(lo, hi);
}
__device__ __forceinline__ void fma2(u64 &d, u64 a, u64 b) {
    asm("fma.rn.f32x2 %0, %1, %2, %0;" : "+l"(d) : "l"(a), "l"(b));
}
__device__ __forceinline__ u64 add2(u64 a, u64 b) {
    u64 r; asm("add.rn.f32x2 %0, %1, %2;" : "=l"(r) : "l"(a), "l"(b)); return r;
}
__device__ __forceinline__ float ex2(float x) {
    float r; asm("ex2.approx.f32 %0, %1;" : "=f"(r) : "f"(x)); return r;
}
__device__ __forceinline__ float rcpa(float x) {
    float r; asm("rcp.approx.f32 %0, %1;" : "=f"(r) : "f"(x)); return r;
}

__global__ void k_zero() {
    int i = blockIdx.x*blockDim.x + threadIdx.x;
    if (i < BATCH*INNER) { g_qsum[i] = 0.f; g_ksum[i] = 0.f; }
    if (i < BATCH*DIM)   { g_xsum[i] = 0.f; }
}

// 128(c) x 128(t) tile GEMM, W pre-duplicated as f32x2 pairs in ws2.
// Thread's 8 t's = {tx*4..+3} and {64+tx*4..+3}  (conflict-free LDS.128).
__device__ __forceinline__ void mm_tile2(const float* __restrict__ xs,
                                         const u64* __restrict__ ws2,
                                         int tx, int ty, u64 acc[8][4]) {
    #pragma unroll 8
    for (int kk = 0; kk < DIM; kk++) {
        ulonglong2 xa = *(const ulonglong2*)&xs[kk*TT + tx*4];
        ulonglong2 xb = *(const ulonglong2*)&xs[kk*TT + 64 + tx*4];
        ulonglong2 w01 = *(const ulonglong2*)&ws2[kk*INNER + ty*8];
        ulonglong2 w23 = *(const ulonglong2*)&ws2[kk*INNER + ty*8 + 2];
        ulonglong2 w45 = *(const ulonglong2*)&ws2[kk*INNER + ty*8 + 4];
        ulonglong2 w67 = *(const ulonglong2*)&ws2[kk*INNER + ty*8 + 6];
        u64 wv[8] = {w01.x, w01.y, w23.x, w23.y, w45.x, w45.y, w67.x, w67.y};
        #pragma unroll
        for (int j = 0; j < 8; j++) {
            fma2(acc[j][0], wv[j], xa.x);
            fma2(acc[j][1], wv[j], xa.y);
            fma2(acc[j][2], wv[j], xb.x);
            fma2(acc[j][3], wv[j], xb.y);
        }
    }
}

// Pass 1: per (b, t-tile): qraw -> exp2 -> E + qsum ; kraw -> per-t head softmax -> ksum ; xsum
__global__ void __launch_bounds__(256) k_reduce(const float* __restrict__ x,
                                                const float* __restrict__ wqkv) {
    extern __shared__ float sm[];
    u64*   ws2 = (u64*)sm;                       // [64][128] u64   64 KB
    float* xs  = sm + 2*DIM*INNER;               // [64][TT]        32 KB
    float* red = xs + DIM*TT;                    // [16][TT]         8 KB
    const int b   = blockIdx.y;
    const int t0  = blockIdx.x * TT;
    const int tid = threadIdx.x;
    const int tx  = tid & 15;   // t quads at tx*4 and 64+tx*4
    const int ty  = tid >> 4;   // c subtile (8 consecutive c each)

    const float* xb = x + (size_t)b*DIM*TLEN + t0;
    for (int idx = tid; idx < DIM*TT; idx += 256) {
        int kk = idx >> 7, t = idx & (TT-1);
        xs[idx] = xb[(size_t)kk*TLEN + t];
    }
    // Wq transposed, *log2e, duplicated to f32x2 pairs
    for (int idx = tid; idx < DIM*INNER; idx += 256) {
        int c = idx >> 6, kk = idx & 63;
        float w = wqkv[idx] * LOG2E;
        ws2[kk*INNER + c] = pack2(w, w);
    }
    __syncthreads();

    if (tid < DIM) {
        float s = 0.f;
        #pragma unroll 8
        for (int t = 0; t < TT; t++) s += xs[tid*TT + t];
        atomicAdd(&g_xsum[b*DIM + tid], s);
    }

    u64 acc[8][4];
    #pragma unroll
    for (int j = 0; j < 8; j++)
        #pragma unroll
        for (int p = 0; p < 4; p++) acc[j][p] = 0ull;

    // ---- Phase A: qraw ----
    mm_tile2(xs, ws2, tx, ty, acc);

    #pragma unroll
    for (int j = 0; j < 8; j++) {
        int c = ty*8 + j;
        float e[8]; float s = 0.f;
        #pragma unroll
        for (int p = 0; p < 4; p++) {
            float2 v = unpack2(acc[j][p]);
            e[2*p]   = ex2(v.x);
            e[2*p+1] = ex2(v.y);
            s += e[2*p] + e[2*p+1];
        }
        #pragma unroll
        for (int off = 8; off > 0; off >>= 1)
            s += __shfl_down_sync(0xffffffffu, s, off, 16);
        if (tx == 0) atomicAdd(&g_qsum[b*INNER + c], s);
        float* eb0 = &g_E[((size_t)b*INNER + c)*TLEN + t0];
        *(float4*)&eb0[tx*4]      = make_float4(e[0], e[1], e[2], e[3]);
        *(float4*)&eb0[64 + tx*4] = make_float4(e[4], e[5], e[6], e[7]);
    }
    __syncthreads();   // all Wq reads done

    // Wk transposed, *log2e, duplicated
    for (int idx = tid; idx < DIM*INNER; idx += 256) {
        int c = idx >> 6, kk = idx & 63;
        float w = wqkv[INNER*DIM + idx] * LOG2E;
        ws2[kk*INNER + c] = pack2(w, w);
    }
    __syncthreads();

    #pragma unroll
    for (int j = 0; j < 8; j++)
        #pragma unroll
        for (int p = 0; p < 4; p++) acc[j][p] = 0ull;

    // ---- Phase B: kraw ----
    mm_tile2(xs, ws2, tx, ty, acc);

    // exp2 + per-t partial sums (packed over t pairs)
    u64 pt2[4] = {0ull, 0ull, 0ull, 0ull};
    #pragma unroll
    for (int j = 0; j < 8; j++)
        #pragma unroll
        for (int p = 0; p < 4; p++) {
            float2 v = unpack2(acc[j][p]);
            u64 e2 = pack2(ex2(v.x), ex2(v.y));
            acc[j][p] = e2;
            pt2[p] = add2(pt2[p], e2);
        }
    // t offsets for p: 0->tx*4, 1->tx*4+2, 2->64+tx*4, 3->64+tx*4+2
    *(u64*)&red[ty*TT + tx*4]          = pt2[0];
    *(u64*)&red[ty*TT + tx*4 + 2]      = pt2[1];
    *(u64*)&red[ty*TT + 64 + tx*4]     = pt2[2];
    *(u64*)&red[ty*TT + 64 + tx*4 + 2] = pt2[3];
    __syncthreads();

    // head sums over d (32 channels = 4 consecutive ty rows) -> 1/hs, then ksum
    const int rb = (ty & ~3)*TT;
    const int toff[4] = {tx*4, tx*4 + 2, 64 + tx*4, 64 + tx*4 + 2};
    u64 inv2[4];
    #pragma unroll
    for (int p = 0; p < 4; p++) {
        int o = rb + toff[p];
        u64 h = add2(add2(*(const u64*)&red[o],
                          *(const u64*)&red[o + TT]),
                     add2(*(const u64*)&red[o + 2*TT],
                          *(const u64*)&red[o + 3*TT]));
        float2 hf = unpack2(h);
        inv2[p] = pack2(rcpa(hf.x), rcpa(hf.y));
    }
    #pragma unroll
    for (int j = 0; j < 8; j++) {
        u64 s2 = 0ull;
        #pragma unroll
        for (int p = 0; p < 4; p++) fma2(s2, acc[j][p], inv2[p]);
        float2 v = unpack2(s2);
        float s = v.x + v.y;
        #pragma unroll
        for (int off = 8; off > 0; off >>= 1)
            s += __shfl_down_sync(0xffffffffu, s, off, 16);
        if (tx == 0) atomicAdd(&g_ksum[b*INNER + ty*8 + j], s);
    }
}

// Pass 2 (tiny): vsum = Wv @ xsum ; A[b][o][c] = w_out[o][c] * ksum*vsum/qsum
__global__ void k_scale(const float* __restrict__ wqkv,
                        const float* __restrict__ wout) {
    int b = blockIdx.x, c = threadIdx.x;   // 128 threads
    __shared__ float ss[INNER];
    float vs = 0.f;
    const float* wv = wqkv + (size_t)(2*INNER + c)*DIM;
    #pragma unroll
    for (int kk = 0; kk < DIM; kk++) vs += wv[kk] * g_xsum[b*DIM + kk];
    ss[c] = g_ksum[b*INNER + c] * vs / g_qsum[b*INNER + c];
    __syncthreads();
    for (int idx = c; idx < 64*INNER; idx += 128) {
        int cc = idx & 127;
        g_A[b*64*INNER + idx] = wout[idx] * ss[cc];
    }
}

// Pass 3: y[b,o,t] = sum_c A[b,o,c] * E[b,c,t] + b_out[o]
// Block: 256t x 32o (o-half per blockIdx.y). Thread: 8t x 4o -> acc = 16 u64 (32 regs).
// E streamed through smem in 4 quarters of 32 c. Conflict-free LDS.
__global__ void __launch_bounds__(256, 3) k_out(const float* __restrict__ bout,
                                                float* __restrict__ y) {
    extern __shared__ float sm[];
    float* Es = sm;                      // [32][TTO]  32 KB (one c-quarter)
    float* As = sm + 32*TTO;             // [128][32]  16 KB (c-major, o inner)
    float* bo = As + INNER*32;           // [32]
    const int b   = blockIdx.z;
    const int o0  = blockIdx.y * 32;
    const int t0  = blockIdx.x * TTO;
    const int tid = threadIdx.x;
    const int tx  = tid & 31;    // t quads at tx*4 and 128+tx*4
    const int ty  = tid >> 5;    // 0..7, 4 o each -> 32 o

    // As fill: lanes walk o (contiguous smem); g_A reads hit L1/L2 (tiny array)
    for (int idx = tid; idx < 32*INNER; idx += 256) {
        int o = idx & 31, c = idx >> 5;
        As[c*32 + o] = g_A[b*64*INNER + (o0 + o)*INNER + c];
    }
    if (tid < 32) bo[tid] = bout[o0 + tid];

    u64 acc[4][4];
    #pragma unroll
    for (int j = 0; j < 4; j++)
        #pragma unroll
        for (int p = 0; p < 4; p++) acc[j][p] = 0ull;

    #pragma unroll
    for (int h = 0; h < 4; h++) {
        const int c0 = h*32;
        __syncthreads();   // (h=0: also covers As/bo fill) Es free to overwrite
        for (int idx = tid; idx < 32*TTO; idx += 256)
            Es[idx] = g_E[((size_t)b*INNER + c0 + (idx >> 8))*TLEN + t0 + (idx & 255)];
        __syncthreads();

        #pragma unroll 8
        for (int cc = 0; cc < 32; cc++) {
            ulonglong2 ea = *(const ulonglong2*)&Es[cc*TTO + tx*4];
            ulonglong2 eb = *(const ulonglong2*)&Es[cc*TTO + 128 + tx*4];
            float4 a0 = *(const float4*)&As[(c0 + cc)*32 + ty*4];
            float af[4] = {a0.x, a0.y, a0.z, a0.w};
            #pragma unroll
            for (int j = 0; j < 4; j++) {
                u64 ad = pack2(af[j], af[j]);
                fma2(acc[j][0], ad, ea.x);
                fma2(acc[j][1], ad, ea.y);
                fma2(acc[j][2], ad, eb.x);
                fma2(acc[j][3], ad, eb.y);
            }
        }
    }

    #pragma unroll
    for (int j = 0; j < 4; j++) {
        int o = o0 + ty*4 + j;
        u64 bb = pack2(bo[ty*4 + j], bo[ty*4 + j]);
        ulonglong2 r0, r1;
        r0.x = add2(acc[j][0], bb); r0.y = add2(acc[j][1], bb);
        r1.x = add2(acc[j][2], bb); r1.y = add2(acc[j][3], bb);
        float* yb = &y[((size_t)b*64 + o)*TLEN + t0];
        *(ulonglong2*)&yb[tx*4]       = r0;
        *(ulonglong2*)&yb[128 + tx*4] = r1;
    }
}

#define SMEM_REDUCE ((2*DIM*INNER + DIM*TT + 16*TT)*4)   /* 106496 */
#define SMEM_OUT    ((32*TTO + INNER*32 + 32)*4)         /*  49280 */

extern "C" void kernel_launch(void* const* d_in, const int* in_sizes, int n_in,
                              void* d_out, int out_size) {
    const float* x    = (const float*)d_in[0];
    const float* wqkv = (const float*)d_in[1];
    const float* wout = (const float*)d_in[2];
    const float* bout = (const float*)d_in[3];
    float* y = (float*)d_out;

    cudaFuncSetAttribute((const void*)k_reduce,
                         cudaFuncAttributeMaxDynamicSharedMemorySize, SMEM_REDUCE);
    cudaFuncSetAttribute((const void*)k_out,
                         cudaFuncAttributeMaxDynamicSharedMemorySize, SMEM_OUT);

    k_zero<<<4, 256>>>();
    dim3 g(NTILES, BATCH);
    k_reduce<<<g, 256, SMEM_REDUCE>>>(x, wqkv);
    k_scale<<<BATCH, 128>>>(wqkv, wout);
    dim3 go(NTILES_O, 2, BATCH);
    k_out<<<go, 256, SMEM_OUT>>>(bout, y);
}

// round 10
// speedup vs baseline: 1.7492x; 1.1631x over previous
#include <cuda_runtime.h>
#include <cstdint>

typedef unsigned long long u64;

#define BATCH 8
#define DIM   64
#define TLEN  16384
#define INNER 128
#define TT    128
#define NTILES (TLEN/TT)
#define TTO   256
#define NTILES_O (TLEN/TTO)
#define LOG2E 1.4426950408889634f

// Scratch (device globals; no runtime allocation)
__device__ float g_E[(size_t)BATCH*INNER*TLEN];   // 64 MB: exp(qraw)
__device__ float g_qsum[BATCH*INNER];
__device__ float g_ksum[BATCH*INNER];
__device__ float g_xsum[BATCH*DIM];
__device__ float g_At[BATCH*INNER*64];            // A transposed: [b][c][o]

// ---- packed fp32x2 helpers (Blackwell) ----
__device__ __forceinline__ u64 pack2(float lo, float hi) {
    u64 r; asm("mov.b64 %0, {%1,%2};" : "=l"(r) : "f"(lo), "f"(hi)); return r;
}
__device__ __forceinline__ float2 unpack2(u64 v) {
    float lo, hi; asm("mov.b64 {%0,%1}, %2;" : "=f"(lo), "=f"(hi) : "l"(v));
    return make_float2(lo, hi);
}
__device__ __forceinline__ void fma2(u64 &d, u64 a, u64 b) {
    asm("fma.rn.f32x2 %0, %1, %2, %0;" : "+l"(d) : "l"(a), "l"(b));
}
__device__ __forceinline__ u64 add2(u64 a, u64 b) {
    u64 r; asm("add.rn.f32x2 %0, %1, %2;" : "=l"(r) : "l"(a), "l"(b)); return r;
}
__device__ __forceinline__ float ex2(float x) {
    float r; asm("ex2.approx.f32 %0, %1;" : "=f"(r) : "f"(x)); return r;
}
__device__ __forceinline__ float rcpa(float x) {
    float r; asm("rcp.approx.f32 %0, %1;" : "=f"(r) : "f"(x)); return r;
}
__device__ __forceinline__ uint32_t smem_u32(const void* p) {
    uint32_t a;
    asm("{ .reg .u64 t; cvta.to.shared.u64 t, %1; cvt.u32.u64 %0, t; }"
        : "=r"(a) : "l"(p));
    return a;
}
__device__ __forceinline__ void cp16(uint32_t dst, const void* src) {
    asm volatile("cp.async.cg.shared.global [%0], [%1], 16;" :: "r"(dst), "l"(src));
}

__global__ void k_zero() {
    int i = blockIdx.x*blockDim.x + threadIdx.x;
    if (i < BATCH*INNER) { g_qsum[i] = 0.f; g_ksum[i] = 0.f; }
    if (i < BATCH*DIM)   { g_xsum[i] = 0.f; }
}

// 128(c) x 128(t) tile GEMM, W pre-duplicated as f32x2 pairs in ws2.
// Thread's 8 t's = {tx*4..+3} and {64+tx*4..+3}  (conflict-free LDS.128).
__device__ __forceinline__ void mm_tile2(const float* __restrict__ xs,
                                         const u64* __restrict__ ws2,
                                         int tx, int ty, u64 acc[8][4]) {
    #pragma unroll 8
    for (int kk = 0; kk < DIM; kk++) {
        ulonglong2 xa = *(const ulonglong2*)&xs[kk*TT + tx*4];
        ulonglong2 xb = *(const ulonglong2*)&xs[kk*TT + 64 + tx*4];
        ulonglong2 w01 = *(const ulonglong2*)&ws2[kk*INNER + ty*8];
        ulonglong2 w23 = *(const ulonglong2*)&ws2[kk*INNER + ty*8 + 2];
        ulonglong2 w45 = *(const ulonglong2*)&ws2[kk*INNER + ty*8 + 4];
        ulonglong2 w67 = *(const ulonglong2*)&ws2[kk*INNER + ty*8 + 6];
        u64 wv[8] = {w01.x, w01.y, w23.x, w23.y, w45.x, w45.y, w67.x, w67.y};
        #pragma unroll
        for (int j = 0; j < 8; j++) {
            fma2(acc[j][0], wv[j], xa.x);
            fma2(acc[j][1], wv[j], xa.y);
            fma2(acc[j][2], wv[j], xb.x);
            fma2(acc[j][3], wv[j], xb.y);
        }
    }
}

// Pass 1: per (b, t-tile): qraw -> exp2 -> E + qsum ; kraw -> per-t head softmax -> ksum ; xsum
__global__ void __launch_bounds__(256) k_reduce(const float* __restrict__ x,
                                                const float* __restrict__ wqkv) {
    extern __shared__ float sm[];
    u64*   ws2 = (u64*)sm;                       // [64][128] u64   64 KB
    float* xs  = sm + 2*DIM*INNER;               // [64][TT]        32 KB
    float* red = xs + DIM*TT;                    // [16][TT]         8 KB
    const int b   = blockIdx.y;
    const int t0  = blockIdx.x * TT;
    const int tid = threadIdx.x;
    const int tx  = tid & 15;   // t quads at tx*4 and 64+tx*4
    const int ty  = tid >> 4;   // c subtile (8 consecutive c each)

    const float* xb = x + (size_t)b*DIM*TLEN + t0;
    for (int idx = tid; idx < DIM*TT; idx += 256) {
        int kk = idx >> 7, t = idx & (TT-1);
        xs[idx] = xb[(size_t)kk*TLEN + t];
    }
    // Wq transposed, *log2e, duplicated to f32x2 pairs
    for (int idx = tid; idx < DIM*INNER; idx += 256) {
        int c = idx >> 6, kk = idx & 63;
        float w = wqkv[idx] * LOG2E;
        ws2[kk*INNER + c] = pack2(w, w);
    }
    __syncthreads();

    if (tid < DIM) {
        float s = 0.f;
        #pragma unroll 8
        for (int t = 0; t < TT; t++) s += xs[tid*TT + t];
        atomicAdd(&g_xsum[b*DIM + tid], s);
    }

    u64 acc[8][4];
    #pragma unroll
    for (int j = 0; j < 8; j++)
        #pragma unroll
        for (int p = 0; p < 4; p++) acc[j][p] = 0ull;

    // ---- Phase A: qraw ----
    mm_tile2(xs, ws2, tx, ty, acc);

    #pragma unroll
    for (int j = 0; j < 8; j++) {
        int c = ty*8 + j;
        float e[8]; float s = 0.f;
        #pragma unroll
        for (int p = 0; p < 4; p++) {
            float2 v = unpack2(acc[j][p]);
            e[2*p]   = ex2(v.x);
            e[2*p+1] = ex2(v.y);
            s += e[2*p] + e[2*p+1];
        }
        #pragma unroll
        for (int off = 8; off > 0; off >>= 1)
            s += __shfl_down_sync(0xffffffffu, s, off, 16);
        if (tx == 0) atomicAdd(&g_qsum[b*INNER + c], s);
        float* eb0 = &g_E[((size_t)b*INNER + c)*TLEN + t0];
        *(float4*)&eb0[tx*4]      = make_float4(e[0], e[1], e[2], e[3]);
        *(float4*)&eb0[64 + tx*4] = make_float4(e[4], e[5], e[6], e[7]);
    }
    __syncthreads();   // all Wq reads done

    // Wk transposed, *log2e, duplicated
    for (int idx = tid; idx < DIM*INNER; idx += 256) {
        int c = idx >> 6, kk = idx & 63;
        float w = wqkv[INNER*DIM + idx] * LOG2E;
        ws2[kk*INNER + c] = pack2(w, w);
    }
    __syncthreads();

    #pragma unroll
    for (int j = 0; j < 8; j++)
        #pragma unroll
        for (int p = 0; p < 4; p++) acc[j][p] = 0ull;

    // ---- Phase B: kraw ----
    mm_tile2(xs, ws2, tx, ty, acc);

    // exp2 + per-t partial sums (packed over t pairs)
    u64 pt2[4] = {0ull, 0ull, 0ull, 0ull};
    #pragma unroll
    for (int j = 0; j < 8; j++)
        #pragma unroll
        for (int p = 0; p < 4; p++) {
            float2 v = unpack2(acc[j][p]);
            u64 e2 = pack2(ex2(v.x), ex2(v.y));
            acc[j][p] = e2;
            pt2[p] = add2(pt2[p], e2);
        }
    // t offsets for p: 0->tx*4, 1->tx*4+2, 2->64+tx*4, 3->64+tx*4+2
    *(u64*)&red[ty*TT + tx*4]          = pt2[0];
    *(u64*)&red[ty*TT + tx*4 + 2]      = pt2[1];
    *(u64*)&red[ty*TT + 64 + tx*4]     = pt2[2];
    *(u64*)&red[ty*TT + 64 + tx*4 + 2] = pt2[3];
    __syncthreads();

    // head sums over d (32 channels = 4 consecutive ty rows) -> 1/hs, then ksum
    const int rb = (ty & ~3)*TT;
    const int toff[4] = {tx*4, tx*4 + 2, 64 + tx*4, 64 + tx*4 + 2};
    u64 inv2[4];
    #pragma unroll
    for (int p = 0; p < 4; p++) {
        int o = rb + toff[p];
        u64 h = add2(add2(*(const u64*)&red[o],
                          *(const u64*)&red[o + TT]),
                     add2(*(const u64*)&red[o + 2*TT],
                          *(const u64*)&red[o + 3*TT]));
        float2 hf = unpack2(h);
        inv2[p] = pack2(rcpa(hf.x), rcpa(hf.y));
    }
    #pragma unroll
    for (int j = 0; j < 8; j++) {
        u64 s2 = 0ull;
        #pragma unroll
        for (int p = 0; p < 4; p++) fma2(s2, acc[j][p], inv2[p]);
        float2 v = unpack2(s2);
        float s = v.x + v.y;
        #pragma unroll
        for (int off = 8; off > 0; off >>= 1)
            s += __shfl_down_sync(0xffffffffu, s, off, 16);
        if (tx == 0) atomicAdd(&g_ksum[b*INNER + ty*8 + j], s);
    }
}

// Pass 2 (tiny): vsum = Wv @ xsum ; A^T[b][c][o] = w_out[o][c] * ksum*vsum/qsum
__global__ void k_scale(const float* __restrict__ wqkv,
                        const float* __restrict__ wout) {
    int b = blockIdx.x, c = threadIdx.x;   // 128 threads
    __shared__ float ss[INNER];
    float vs = 0.f;
    const float* wv = wqkv + (size_t)(2*INNER + c)*DIM;
    #pragma unroll
    for (int kk = 0; kk < DIM; kk++) vs += wv[kk] * g_xsum[b*DIM + kk];
    ss[c] = g_ksum[b*INNER + c] * vs / g_qsum[b*INNER + c];
    __syncthreads();
    for (int idx = c; idx < INNER*64; idx += 128) {
        int cc = idx >> 6, o = idx & 63;
        g_At[(size_t)b*INNER*64 + idx] = wout[o*INNER + cc] * ss[cc];
    }
}

// Pass 3: y[b,o,t] = sum_c A[b,o,c] * E[b,c,t] + b_out[o]
// 256t x 64o tile per block; E streamed in 4 stages of 32c, DOUBLE-BUFFERED
// via cp.async (fill of stage h+1 overlaps compute of stage h).
// Thread: 8t ({tx*4..+3} and {128+tx*4..+3}) x 8o (ty*8..+7). Conflict-free LDS.
__global__ void __launch_bounds__(256) k_out(const float* __restrict__ bout,
                                             float* __restrict__ y) {
    extern __shared__ float sm[];
    float* Es0 = sm;                          // [32][TTO] 32 KB
    float* Es1 = sm + 32*TTO;                 // [32][TTO] 32 KB
    float* As  = sm + 2*32*TTO;               // [128][64] 32 KB (c-major, o inner)
    float* bo  = As + INNER*64;               // [64]
    const int b   = blockIdx.y;
    const int t0  = blockIdx.x * TTO;
    const int tid = threadIdx.x;
    const int tx  = tid & 31;    // t quads at tx*4 and 128+tx*4
    const int ty  = tid >> 5;    // 8 o each -> 64 o

    // As fill: straight float4 copy of g_At slice (same layout)
    {
        const float4* s4 = (const float4*)&g_At[(size_t)b*INNER*64];
        float4* d4 = (float4*)As;
        #pragma unroll
        for (int i = 0; i < (INNER*64/4)/256; i++)   // 8 iters
            d4[tid + i*256] = s4[tid + i*256];
    }
    if (tid < 64) bo[tid] = bout[tid];

    const uint32_t esb0 = smem_u32(Es0);
    const uint32_t esb1 = smem_u32(Es1);
    const float* Ebase = &g_E[(size_t)b*INNER*TLEN + t0];

    // prefetch stage 0 into Es0
    #pragma unroll
    for (int i = 0; i < 8; i++) {
        int idx = tid + i*256;              // 0..2047 -> c = idx>>6, 16B-chunk = idx&63
        cp16(esb0 + idx*16, Ebase + (size_t)(idx >> 6)*TLEN + (idx & 63)*4);
    }
    asm volatile("cp.async.commit_group;" ::: "memory");

    u64 acc[8][4];
    #pragma unroll
    for (int j = 0; j < 8; j++)
        #pragma unroll
        for (int p = 0; p < 4; p++) acc[j][p] = 0ull;

    #pragma unroll
    for (int h = 0; h < 4; h++) {
        if (h < 3) {
            const uint32_t dst = ((h+1) & 1) ? esb1 : esb0;
            #pragma unroll
            for (int i = 0; i < 8; i++) {
                int idx = tid + i*256;
                cp16(dst + idx*16,
                     Ebase + (size_t)((h+1)*32 + (idx >> 6))*TLEN + (idx & 63)*4);
            }
            asm volatile("cp.async.commit_group;" ::: "memory");
            asm volatile("cp.async.wait_group 1;" ::: "memory");
        } else {
            asm volatile("cp.async.wait_group 0;" ::: "memory");
        }
        __syncthreads();   // stage h visible to all (h=0: also covers As/bo fill)

        const float* Eb = (h & 1) ? Es1 : Es0;
        #pragma unroll 4
        for (int cc = 0; cc < 32; cc++) {
            ulonglong2 ea = *(const ulonglong2*)&Eb[cc*TTO + tx*4];
            ulonglong2 eb = *(const ulonglong2*)&Eb[cc*TTO + 128 + tx*4];
            float4 a0 = *(const float4*)&As[(h*32 + cc)*64 + ty*8];
            float4 a1 = *(const float4*)&As[(h*32 + cc)*64 + ty*8 + 4];
            float af[8] = {a0.x,a0.y,a0.z,a0.w,a1.x,a1.y,a1.z,a1.w};
            #pragma unroll
            for (int j = 0; j < 8; j++) {
                u64 ad = pack2(af[j], af[j]);
                fma2(acc[j][0], ad, ea.x);
                fma2(acc[j][1], ad, ea.y);
                fma2(acc[j][2], ad, eb.x);
                fma2(acc[j][3], ad, eb.y);
            }
        }
        __syncthreads();   // all reads of this buffer done before refill
    }

    #pragma unroll
    for (int j = 0; j < 8; j++) {
        int o = ty*8 + j;
        u64 bb = pack2(bo[o], bo[o]);
        ulonglong2 r0, r1;
        r0.x = add2(acc[j][0], bb); r0.y = add2(acc[j][1], bb);
        r1.x = add2(acc[j][2], bb); r1.y = add2(acc[j][3], bb);
        float* yb = &y[((size_t)b*64 + o)*TLEN + t0];
        *(ulonglong2*)&yb[tx*4]       = r0;
        *(ulonglong2*)&yb[128 + tx*4] = r1;
    }
}

#define SMEM_REDUCE ((2*DIM*INNER + DIM*TT + 16*TT)*4)   /* 106496 */
#define SMEM_OUT    ((2*32*TTO + INNER*64 + 64)*4)       /*  98560 */

extern "C" void kernel_launch(void* const* d_in, const int* in_sizes, int n_in,
                              void* d_out, int out_size) {
    const float* x    = (const float*)d_in[0];
    const float* wqkv = (const float*)d_in[1];
    const float* wout = (const float*)d_in[2];
    const float* bout = (const float*)d_in[3];
    float* y = (float*)d_out;

    cudaFuncSetAttribute((const void*)k_reduce,
                         cudaFuncAttributeMaxDynamicSharedMemorySize, SMEM_REDUCE);
    cudaFuncSetAttribute((const void*)k_out,
                         cudaFuncAttributeMaxDynamicSharedMemorySize, SMEM_OUT);

    k_zero<<<4, 256>>>();
    dim3 g(NTILES, BATCH);
    k_reduce<<<g, 256, SMEM_REDUCE>>>(x, wqkv);
    k_scale<<<BATCH, 128>>>(wqkv, wout);
    dim3 go(NTILES_O, BATCH);
    k_out<<<go, 256, SMEM_OUT>>>(bout, y);
}

// round 11
// speedup vs baseline: 2.5243x; 1.4432x over previous
#include <cuda_runtime.h>
#include <cstdint>

typedef unsigned long long u64;

#define BATCH 8
#define DIM   64
#define TLEN  16384
#define INNER 128
#define TT    128
#define NTILES (TLEN/TT)
#define TTO   256
#define NTILES_O (TLEN/TTO)
#define LOG2E 1.4426950408889634f

// Scratch (device globals; no runtime allocation)
__device__ float g_E[(size_t)BATCH*INNER*TLEN];   // 64 MB: exp(qraw)
__device__ float g_qsum[BATCH*INNER];
__device__ float g_ksum[BATCH*INNER];
__device__ float g_xsum[BATCH*DIM];
__device__ float g_At[BATCH*INNER*64];            // A transposed: [b][c][o]
__device__ float g_W2[2*DIM*INNER];               // [w][kk][c]: transposed, *log2e

// ---- packed fp32x2 helpers (Blackwell) ----
__device__ __forceinline__ u64 pack2(float lo, float hi) {
    u64 r; asm("mov.b64 %0, {%1,%2};" : "=l"(r) : "f"(lo), "f"(hi)); return r;
}
__device__ __forceinline__ float2 unpack2(u64 v) {
    float lo, hi; asm("mov.b64 {%0,%1}, %2;" : "=f"(lo), "=f"(hi) : "l"(v));
    return make_float2(lo, hi);
}
__device__ __forceinline__ void fma2(u64 &d, u64 a, u64 b) {
    asm("fma.rn.f32x2 %0, %1, %2, %0;" : "+l"(d) : "l"(a), "l"(b));
}
__device__ __forceinline__ u64 add2(u64 a, u64 b) {
    u64 r; asm("add.rn.f32x2 %0, %1, %2;" : "=l"(r) : "l"(a), "l"(b)); return r;
}
__device__ __forceinline__ float ex2(float x) {
    float r; asm("ex2.approx.f32 %0, %1;" : "=f"(r) : "f"(x)); return r;
}
__device__ __forceinline__ float rcpa(float x) {
    float r; asm("rcp.approx.f32 %0, %1;" : "=f"(r) : "f"(x)); return r;
}
__device__ __forceinline__ uint32_t smem_u32(const void* p) {
    uint32_t a;
    asm("{ .reg .u64 t; cvta.to.shared.u64 t, %1; cvt.u32.u64 %0, t; }"
        : "=r"(a) : "l"(p));
    return a;
}
__device__ __forceinline__ void cp16(uint32_t dst, const void* src) {
    asm volatile("cp.async.cg.shared.global [%0], [%1], 16;" :: "r"(dst), "l"(src));
}
#define CP_COMMIT() asm volatile("cp.async.commit_group;" ::: "memory")
#define CP_WAIT(N)  asm volatile("cp.async.wait_group %0;" :: "n"(N) : "memory")

__global__ void k_zero() {
    int i = blockIdx.x*blockDim.x + threadIdx.x;
    if (i < BATCH*INNER) { g_qsum[i] = 0.f; g_ksum[i] = 0.f; }
    if (i < BATCH*DIM)   { g_xsum[i] = 0.f; }
}

// Pre-transform W: g_W2[w][kk][c] = wqkv[w*INNER*DIM + c*DIM + kk] * log2e
__global__ void k_prep(const float* __restrict__ wqkv) {
    int tid = threadIdx.x;
    for (int idx = tid; idx < 2*DIM*INNER; idx += 256) {
        int w = idx >> 13;
        int r = idx & 8191;
        int kk = r >> 7, c = r & 127;
        g_W2[idx] = wqkv[w*INNER*DIM + c*DIM + kk] * LOG2E;
    }
}

// 128(c) x 128(t) tile GEMM; W fp32 in smem, duplicated to f32x2 in regs.
// Thread's 8 t's = {tx*4..+3} and {64+tx*4..+3}  (conflict-free LDS.128).
__device__ __forceinline__ void mm_tile3(const float* __restrict__ xs,
                                         const float* __restrict__ ws,
                                         int tx, int ty, u64 acc[8][4]) {
    #pragma unroll 8
    for (int kk = 0; kk < DIM; kk++) {
        ulonglong2 xa = *(const ulonglong2*)&xs[kk*TT + tx*4];
        ulonglong2 xb = *(const ulonglong2*)&xs[kk*TT + 64 + tx*4];
        float4 w0 = *(const float4*)&ws[kk*INNER + ty*8];
        float4 w1 = *(const float4*)&ws[kk*INNER + ty*8 + 4];
        float wf[8] = {w0.x,w0.y,w0.z,w0.w,w1.x,w1.y,w1.z,w1.w};
        #pragma unroll
        for (int j = 0; j < 8; j++) {
            u64 wd = pack2(wf[j], wf[j]);
            fma2(acc[j][0], wd, xa.x);
            fma2(acc[j][1], wd, xa.y);
            fma2(acc[j][2], wd, xb.x);
            fma2(acc[j][3], wd, xb.y);
        }
    }
}

// Pass 1: per (b, t-tile): qraw -> exp2 -> E + qsum ; kraw -> per-t head softmax -> ksum ; xsum
// Both W buffers + x filled via one cp.async group at start; NO mid-kernel reload.
__global__ void __launch_bounds__(256) k_reduce(const float* __restrict__ x) {
    extern __shared__ float sm[];
    float* wsq = sm;                 // [64][128] 32 KB
    float* wsk = sm + DIM*INNER;     // [64][128] 32 KB
    float* xs  = sm + 2*DIM*INNER;   // [64][TT]  32 KB
    float* red = xs + DIM*TT;        // [16][TT]   8 KB
    const int b   = blockIdx.y;
    const int t0  = blockIdx.x * TT;
    const int tid = threadIdx.x;
    const int tx  = tid & 15;   // t quads at tx*4 and 64+tx*4
    const int ty  = tid >> 4;   // c subtile (8 consecutive c each)

    // ---- async fills: wsq, wsk (straight copies), xs (row-chunked) ----
    {
        const uint32_t s_wsq = smem_u32(wsq) + tid*16;
        const uint32_t s_wsk = smem_u32(wsk) + tid*16;
        const uint32_t s_xs  = smem_u32(xs)  + tid*16;
        const char* wq = (const char*)g_W2 + tid*16;
        const char* wk = (const char*)(g_W2 + DIM*INNER) + tid*16;
        const float* xb = x + (size_t)b*DIM*TLEN + t0;
        // x chunk idx = tid + i*256: kk = idx>>5 = (tid>>5) + 8i, off = tid&31
        const char* xp = (const char*)(xb + (size_t)(tid >> 5)*TLEN) + (tid & 31)*16;
        #pragma unroll
        for (int i = 0; i < 8; i++) {
            cp16(s_wsq + i*4096, wq + i*4096);
            cp16(s_wsk + i*4096, wk + i*4096);
            cp16(s_xs  + i*4096, xp + (size_t)(8*i)*TLEN*4);
        }
        CP_COMMIT();
        CP_WAIT(0);
    }
    __syncthreads();

    // xsum: conflict-free — thread (kk = tid>>2, q = tid&3) sums 32 contiguous
    // floats of row kk, with XOR-swizzled chunk order to spread banks.
    {
        int kk = tid >> 2, q = tid & 3;
        const float* xrow = xs + kk*TT + q*32;
        float s = 0.f;
        #pragma unroll
        for (int i = 0; i < 8; i++) {
            int j = (i + kk) & 7;
            float4 v = *(const float4*)&xrow[j*4];
            s += (v.x + v.y) + (v.z + v.w);
        }
        s += __shfl_down_sync(0xffffffffu, s, 2, 4);
        s += __shfl_down_sync(0xffffffffu, s, 1, 4);
        if (q == 0) atomicAdd(&g_xsum[b*DIM + kk], s);
    }

    u64 acc[8][4];
    #pragma unroll
    for (int j = 0; j < 8; j++)
        #pragma unroll
        for (int p = 0; p < 4; p++) acc[j][p] = 0ull;

    // ---- Phase A: qraw ----
    mm_tile3(xs, wsq, tx, ty, acc);

    #pragma unroll
    for (int j = 0; j < 8; j++) {
        int c = ty*8 + j;
        float e[8]; float s = 0.f;
        #pragma unroll
        for (int p = 0; p < 4; p++) {
            float2 v = unpack2(acc[j][p]);
            e[2*p]   = ex2(v.x);
            e[2*p+1] = ex2(v.y);
            s += e[2*p] + e[2*p+1];
        }
        #pragma unroll
        for (int off = 8; off > 0; off >>= 1)
            s += __shfl_down_sync(0xffffffffu, s, off, 16);
        if (tx == 0) atomicAdd(&g_qsum[b*INNER + c], s);
        float* eb0 = &g_E[((size_t)b*INNER + c)*TLEN + t0];
        *(float4*)&eb0[tx*4]      = make_float4(e[0], e[1], e[2], e[3]);
        *(float4*)&eb0[64 + tx*4] = make_float4(e[4], e[5], e[6], e[7]);
    }

    // ---- Phase B: kraw (wsk already resident; no barrier needed) ----
    #pragma unroll
    for (int j = 0; j < 8; j++)
        #pragma unroll
        for (int p = 0; p < 4; p++) acc[j][p] = 0ull;

    mm_tile3(xs, wsk, tx, ty, acc);

    // exp2 + per-t partial sums (packed over t pairs)
    u64 pt2[4] = {0ull, 0ull, 0ull, 0ull};
    #pragma unroll
    for (int j = 0; j < 8; j++)
        #pragma unroll
        for (int p = 0; p < 4; p++) {
            float2 v = unpack2(acc[j][p]);
            u64 e2 = pack2(ex2(v.x), ex2(v.y));
            acc[j][p] = e2;
            pt2[p] = add2(pt2[p], e2);
        }
    // t offsets for p: 0->tx*4, 1->tx*4+2, 2->64+tx*4, 3->64+tx*4+2
    *(u64*)&red[ty*TT + tx*4]          = pt2[0];
    *(u64*)&red[ty*TT + tx*4 + 2]      = pt2[1];
    *(u64*)&red[ty*TT + 64 + tx*4]     = pt2[2];
    *(u64*)&red[ty*TT + 64 + tx*4 + 2] = pt2[3];
    __syncthreads();

    // head sums over d (32 channels = 4 consecutive ty rows) -> 1/hs, then ksum
    const int rb = (ty & ~3)*TT;
    const int toff[4] = {tx*4, tx*4 + 2, 64 + tx*4, 64 + tx*4 + 2};
    u64 inv2[4];
    #pragma unroll
    for (int p = 0; p < 4; p++) {
        int o = rb + toff[p];
        u64 h = add2(add2(*(const u64*)&red[o],
                          *(const u64*)&red[o + TT]),
                     add2(*(const u64*)&red[o + 2*TT],
                          *(const u64*)&red[o + 3*TT]));
        float2 hf = unpack2(h);
        inv2[p] = pack2(rcpa(hf.x), rcpa(hf.y));
    }
    #pragma unroll
    for (int j = 0; j < 8; j++) {
        u64 s2 = 0ull;
        #pragma unroll
        for (int p = 0; p < 4; p++) fma2(s2, acc[j][p], inv2[p]);
        float2 v = unpack2(s2);
        float s = v.x + v.y;
        #pragma unroll
        for (int off = 8; off > 0; off >>= 1)
            s += __shfl_down_sync(0xffffffffu, s, off, 16);
        if (tx == 0) atomicAdd(&g_ksum[b*INNER + ty*8 + j], s);
    }
}

// Pass 2 (tiny): vsum = Wv @ xsum ; A^T[b][c][o] = w_out[o][c] * ksum*vsum/qsum
__global__ void k_scale(const float* __restrict__ wqkv,
                        const float* __restrict__ wout) {
    int b = blockIdx.x, c = threadIdx.x;   // 128 threads
    __shared__ float ss[INNER];
    float vs = 0.f;
    const float* wv = wqkv + (size_t)(2*INNER + c)*DIM;
    #pragma unroll
    for (int kk = 0; kk < DIM; kk++) vs += wv[kk] * g_xsum[b*DIM + kk];
    ss[c] = g_ksum[b*INNER + c] * vs / g_qsum[b*INNER + c];
    __syncthreads();
    for (int idx = c; idx < INNER*64; idx += 128) {
        int cc = idx >> 6, o = idx & 63;
        g_At[(size_t)b*INNER*64 + idx] = wout[o*INNER + cc] * ss[cc];
    }
}

// Pass 3: y[b,o,t] = sum_c A[b,o,c] * E[b,c,t] + b_out[o]
// 256t x 64o tile per block; E streamed in 4 stages of 32c, double-buffered
// via cp.async. Addresses decomposed to base(tid)+immediates to keep regs <128.
__global__ void __launch_bounds__(256, 2) k_out(const float* __restrict__ bout,
                                                float* __restrict__ y) {
    extern __shared__ float sm[];
    float* Es0 = sm;                          // [32][TTO] 32 KB
    float* Es1 = sm + 32*TTO;                 // [32][TTO] 32 KB
    float* As  = sm + 2*32*TTO;               // [128][64] 32 KB (c-major, o inner)
    float* bo  = As + INNER*64;               // [64]
    const int b   = blockIdx.y;
    const int t0  = blockIdx.x * TTO;
    const int tid = threadIdx.x;
    const int tx  = tid & 31;    // t quads at tx*4 and 128+tx*4
    const int ty  = tid >> 5;    // 8 o each -> 64 o

    // Per-thread base pointers; all stage/iter offsets are immediates.
    const float* Ebase = &g_E[(size_t)b*INNER*TLEN + t0];
    const char* psrc = (const char*)Ebase
                     + ((size_t)(tid >> 6)*TLEN + (size_t)(tid & 63)*4)*4;
    const char* asrc = (const char*)&g_At[(size_t)b*INNER*64] + tid*16;
    const uint32_t d0 = smem_u32(Es0) + tid*16;
    const uint32_t d1 = smem_u32(Es1) + tid*16;
    const uint32_t da = smem_u32(As)  + tid*16;

    // group 0: As (32KB) + E stage 0 (32KB)
    #pragma unroll
    for (int i = 0; i < 8; i++) {
        cp16(da + i*4096, asrc + i*4096);
        cp16(d0 + i*4096, psrc + (size_t)(4*i)*TLEN*4);
    }
    CP_COMMIT();
    if (tid < 64) bo[tid] = bout[tid];

    u64 acc[8][4];
    #pragma unroll
    for (int j = 0; j < 8; j++)
        #pragma unroll
        for (int p = 0; p < 4; p++) acc[j][p] = 0ull;

    #pragma unroll
    for (int h = 0; h < 4; h++) {
        if (h < 3) {
            const uint32_t dst = ((h+1) & 1) ? d1 : d0;
            #pragma unroll
            for (int i = 0; i < 8; i++)
                cp16(dst + i*4096, psrc + (size_t)((h+1)*32 + 4*i)*TLEN*4);
            CP_COMMIT();
            CP_WAIT(1);
        } else {
            CP_WAIT(0);
        }
        __syncthreads();   // stage h visible (h=0: also covers As/bo)

        const float* Eb = (h & 1) ? Es1 : Es0;
        const float* Ah = As + h*32*64 + ty*8;
        #pragma unroll 4
        for (int cc = 0; cc < 32; cc++) {
            ulonglong2 ea = *(const ulonglong2*)&Eb[cc*TTO + tx*4];
            ulonglong2 eb = *(const ulonglong2*)&Eb[cc*TTO + 128 + tx*4];
            float4 a0 = *(const float4*)&Ah[cc*64];
            float4 a1 = *(const float4*)&Ah[cc*64 + 4];
            float af[8] = {a0.x,a0.y,a0.z,a0.w,a1.x,a1.y,a1.z,a1.w};
            #pragma unroll
            for (int j = 0; j < 8; j++) {
                u64 ad = pack2(af[j], af[j]);
                fma2(acc[j][0], ad, ea.x);
                fma2(acc[j][1], ad, ea.y);
                fma2(acc[j][2], ad, eb.x);
                fma2(acc[j][3], ad, eb.y);
            }
        }
        __syncthreads();   // reads done before refill of this buffer
    }

    #pragma unroll
    for (int j = 0; j < 8; j++) {
        int o = ty*8 + j;
        u64 bb = pack2(bo[o], bo[o]);
        ulonglong2 r0, r1;
        r0.x = add2(acc[j][0], bb); r0.y = add2(acc[j][1], bb);
        r1.x = add2(acc[j][2], bb); r1.y = add2(acc[j][3], bb);
        float* yb = &y[((size_t)b*64 + o)*TLEN + t0];
        *(ulonglong2*)&yb[tx*4]       = r0;
        *(ulonglong2*)&yb[128 + tx*4] = r1;
    }
}

#define SMEM_REDUCE ((2*DIM*INNER + DIM*TT + 16*TT)*4)   /* 106496 */
#define SMEM_OUT    ((2*32*TTO + INNER*64 + 64)*4)       /*  98560 */

extern "C" void kernel_launch(void* const* d_in, const int* in_sizes, int n_in,
                              void* d_out, int out_size) {
    const float* x    = (const float*)d_in[0];
    const float* wqkv = (const float*)d_in[1];
    const float* wout = (const float*)d_in[2];
    const float* bout = (const float*)d_in[3];
    float* y = (float*)d_out;

    cudaFuncSetAttribute((const void*)k_reduce,
                         cudaFuncAttributeMaxDynamicSharedMemorySize, SMEM_REDUCE);
    cudaFuncSetAttribute((const void*)k_out,
                         cudaFuncAttributeMaxDynamicSharedMemorySize, SMEM_OUT);

    k_zero<<<4, 256>>>();
    k_prep<<<1, 256>>>(wqkv);
    dim3 g(NTILES, BATCH);
    k_reduce<<<g, 256, SMEM_REDUCE>>>(x);
    k_scale<<<BATCH, 128>>>(wqkv, wout);
    dim3 go(NTILES_O, BATCH);
    k_out<<<go, 256, SMEM_OUT>>>(bout, y);
}

// round 12
// speedup vs baseline: 2.7688x; 1.0968x over previous
#include <cuda_runtime.h>
#include <cstdint>

typedef unsigned long long u64;

#define BATCH 8
#define DIM   64
#define TLEN  16384
#define INNER 128
#define TT    128
#define NTILES (TLEN/TT)
#define TTO   256
#define NTILES_O (TLEN/TTO)
#define LOG2E 1.4426950408889634f

// Scratch (device globals; no runtime allocation)
__device__ float g_E[(size_t)BATCH*INNER*TLEN];   // 64 MB: exp(qraw)
__device__ float g_qsum[BATCH*INNER];
__device__ float g_ksum[BATCH*INNER];
__device__ float g_xsum[BATCH*DIM];
__device__ float g_At[BATCH*INNER*64];            // A transposed: [b][c][o]
__device__ float g_W2[2*DIM*INNER];               // [w][kk][c]: transposed, *log2e

// ---- packed fp32x2 helpers (Blackwell) ----
__device__ __forceinline__ u64 pack2(float lo, float hi) {
    u64 r; asm("mov.b64 %0, {%1,%2};" : "=l"(r) : "f"(lo), "f"(hi)); return r;
}
__device__ __forceinline__ float2 unpack2(u64 v) {
    float lo, hi; asm("mov.b64 {%0,%1}, %2;" : "=f"(lo), "=f"(hi) : "l"(v));
    return make_float2(lo, hi);
}
__device__ __forceinline__ void fma2(u64 &d, u64 a, u64 b) {
    asm("fma.rn.f32x2 %0, %1, %2, %0;" : "+l"(d) : "l"(a), "l"(b));
}
__device__ __forceinline__ u64 add2(u64 a, u64 b) {
    u64 r; asm("add.rn.f32x2 %0, %1, %2;" : "=l"(r) : "l"(a), "l"(b)); return r;
}
__device__ __forceinline__ float ex2(float x) {
    float r; asm("ex2.approx.f32 %0, %1;" : "=f"(r) : "f"(x)); return r;
}
__device__ __forceinline__ float rcpa(float x) {
    float r; asm("rcp.approx.f32 %0, %1;" : "=f"(r) : "f"(x)); return r;
}
__device__ __forceinline__ uint32_t smem_u32(const void* p) {
    uint32_t a;
    asm("{ .reg .u64 t; cvta.to.shared.u64 t, %1; cvt.u32.u64 %0, t; }"
        : "=r"(a) : "l"(p));
    return a;
}
__device__ __forceinline__ void cp16(uint32_t dst, const void* src) {
    asm volatile("cp.async.cg.shared.global [%0], [%1], 16;" :: "r"(dst), "l"(src));
}
#define CP_COMMIT() asm volatile("cp.async.commit_group;" ::: "memory")
#define CP_WAIT(N)  asm volatile("cp.async.wait_group %0;" :: "n"(N) : "memory")

// Merged setup: zero accumulators + pre-transform W (transpose + *log2e).
__global__ void k_setup(const float* __restrict__ wqkv) {
    int i = blockIdx.x*blockDim.x + threadIdx.x;
    if (i < BATCH*INNER) { g_qsum[i] = 0.f; g_ksum[i] = 0.f; }
    if (i < BATCH*DIM)   { g_xsum[i] = 0.f; }
    // 2*DIM*INNER = 16384 elements over gridDim.x*256 threads
    for (int idx = i; idx < 2*DIM*INNER; idx += gridDim.x*blockDim.x) {
        int w = idx >> 13;
        int r = idx & 8191;
        int kk = r >> 7, c = r & 127;
        g_W2[idx] = wqkv[w*INNER*DIM + c*DIM + kk] * LOG2E;
    }
}

// 128(c) x 128(t) tile GEMM; W fp32 in smem, duplicated to f32x2 in regs.
// Thread's 8 t's = {tx*4..+3} and {64+tx*4..+3}  (conflict-free LDS.128).
__device__ __forceinline__ void mm_tile3(const float* __restrict__ xs,
                                         const float* __restrict__ ws,
                                         int tx, int ty, u64 acc[8][4]) {
    #pragma unroll 8
    for (int kk = 0; kk < DIM; kk++) {
        ulonglong2 xa = *(const ulonglong2*)&xs[kk*TT + tx*4];
        ulonglong2 xb = *(const ulonglong2*)&xs[kk*TT + 64 + tx*4];
        float4 w0 = *(const float4*)&ws[kk*INNER + ty*8];
        float4 w1 = *(const float4*)&ws[kk*INNER + ty*8 + 4];
        float wf[8] = {w0.x,w0.y,w0.z,w0.w,w1.x,w1.y,w1.z,w1.w};
        #pragma unroll
        for (int j = 0; j < 8; j++) {
            u64 wd = pack2(wf[j], wf[j]);
            fma2(acc[j][0], wd, xa.x);
            fma2(acc[j][1], wd, xa.y);
            fma2(acc[j][2], wd, xb.x);
            fma2(acc[j][3], wd, xb.y);
        }
    }
}

// Pass 1: per (b, t-tile): qraw -> exp2 -> E + qsum ; kraw -> per-t head softmax -> ksum ; xsum
// Both W buffers + x filled via one cp.async group at start; NO mid-kernel reload.
__global__ void __launch_bounds__(256) k_reduce(const float* __restrict__ x) {
    extern __shared__ float sm[];
    float* wsq = sm;                 // [64][128] 32 KB
    float* wsk = sm + DIM*INNER;     // [64][128] 32 KB
    float* xs  = sm + 2*DIM*INNER;   // [64][TT]  32 KB
    float* red = xs + DIM*TT;        // [16][TT]   8 KB
    const int b   = blockIdx.y;
    const int t0  = blockIdx.x * TT;
    const int tid = threadIdx.x;
    const int tx  = tid & 15;   // t quads at tx*4 and 64+tx*4
    const int ty  = tid >> 4;   // c subtile (8 consecutive c each)

    // ---- async fills: wsq, wsk (straight copies), xs (row-chunked) ----
    {
        const uint32_t s_wsq = smem_u32(wsq) + tid*16;
        const uint32_t s_wsk = smem_u32(wsk) + tid*16;
        const uint32_t s_xs  = smem_u32(xs)  + tid*16;
        const char* wq = (const char*)g_W2 + tid*16;
        const char* wk = (const char*)(g_W2 + DIM*INNER) + tid*16;
        const float* xb = x + (size_t)b*DIM*TLEN + t0;
        // x chunk idx = tid + i*256: kk = idx>>5 = (tid>>5) + 8i, off = tid&31
        const char* xp = (const char*)(xb + (size_t)(tid >> 5)*TLEN) + (tid & 31)*16;
        #pragma unroll
        for (int i = 0; i < 8; i++) {
            cp16(s_wsq + i*4096, wq + i*4096);
            cp16(s_wsk + i*4096, wk + i*4096);
            cp16(s_xs  + i*4096, xp + (size_t)(8*i)*TLEN*4);
        }
        CP_COMMIT();
        CP_WAIT(0);
    }
    __syncthreads();

    // xsum: conflict-free — thread (kk = tid>>2, q = tid&3) sums 32 contiguous
    // floats of row kk, with XOR-swizzled chunk order to spread banks.
    {
        int kk = tid >> 2, q = tid & 3;
        const float* xrow = xs + kk*TT + q*32;
        float s = 0.f;
        #pragma unroll
        for (int i = 0; i < 8; i++) {
            int j = (i + kk) & 7;
            float4 v = *(const float4*)&xrow[j*4];
            s += (v.x + v.y) + (v.z + v.w);
        }
        s += __shfl_down_sync(0xffffffffu, s, 2, 4);
        s += __shfl_down_sync(0xffffffffu, s, 1, 4);
        if (q == 0) atomicAdd(&g_xsum[b*DIM + kk], s);
    }

    u64 acc[8][4];
    #pragma unroll
    for (int j = 0; j < 8; j++)
        #pragma unroll
        for (int p = 0; p < 4; p++) acc[j][p] = 0ull;

    // ---- Phase A: qraw ----
    mm_tile3(xs, wsq, tx, ty, acc);

    #pragma unroll
    for (int j = 0; j < 8; j++) {
        int c = ty*8 + j;
        float e[8]; float s = 0.f;
        #pragma unroll
        for (int p = 0; p < 4; p++) {
            float2 v = unpack2(acc[j][p]);
            e[2*p]   = ex2(v.x);
            e[2*p+1] = ex2(v.y);
            s += e[2*p] + e[2*p+1];
        }
        #pragma unroll
        for (int off = 8; off > 0; off >>= 1)
            s += __shfl_down_sync(0xffffffffu, s, off, 16);
        if (tx == 0) atomicAdd(&g_qsum[b*INNER + c], s);
        float* eb0 = &g_E[((size_t)b*INNER + c)*TLEN + t0];
        *(float4*)&eb0[tx*4]      = make_float4(e[0], e[1], e[2], e[3]);
        *(float4*)&eb0[64 + tx*4] = make_float4(e[4], e[5], e[6], e[7]);
    }

    // ---- Phase B: kraw (wsk already resident; no barrier needed) ----
    #pragma unroll
    for (int j = 0; j < 8; j++)
        #pragma unroll
        for (int p = 0; p < 4; p++) acc[j][p] = 0ull;

    mm_tile3(xs, wsk, tx, ty, acc);

    // exp2 + per-t partial sums (packed over t pairs)
    u64 pt2[4] = {0ull, 0ull, 0ull, 0ull};
    #pragma unroll
    for (int j = 0; j < 8; j++)
        #pragma unroll
        for (int p = 0; p < 4; p++) {
            float2 v = unpack2(acc[j][p]);
            u64 e2 = pack2(ex2(v.x), ex2(v.y));
            acc[j][p] = e2;
            pt2[p] = add2(pt2[p], e2);
        }
    // t offsets for p: 0->tx*4, 1->tx*4+2, 2->64+tx*4, 3->64+tx*4+2
    *(u64*)&red[ty*TT + tx*4]          = pt2[0];
    *(u64*)&red[ty*TT + tx*4 + 2]      = pt2[1];
    *(u64*)&red[ty*TT + 64 + tx*4]     = pt2[2];
    *(u64*)&red[ty*TT + 64 + tx*4 + 2] = pt2[3];
    __syncthreads();

    // head sums over d (32 channels = 4 consecutive ty rows) -> 1/hs, then ksum
    const int rb = (ty & ~3)*TT;
    const int toff[4] = {tx*4, tx*4 + 2, 64 + tx*4, 64 + tx*4 + 2};
    u64 inv2[4];
    #pragma unroll
    for (int p = 0; p < 4; p++) {
        int o = rb + toff[p];
        u64 h = add2(add2(*(const u64*)&red[o],
                          *(const u64*)&red[o + TT]),
                     add2(*(const u64*)&red[o + 2*TT],
                          *(const u64*)&red[o + 3*TT]));
        float2 hf = unpack2(h);
        inv2[p] = pack2(rcpa(hf.x), rcpa(hf.y));
    }
    #pragma unroll
    for (int j = 0; j < 8; j++) {
        u64 s2 = 0ull;
        #pragma unroll
        for (int p = 0; p < 4; p++) fma2(s2, acc[j][p], inv2[p]);
        float2 v = unpack2(s2);
        float s = v.x + v.y;
        #pragma unroll
        for (int off = 8; off > 0; off >>= 1)
            s += __shfl_down_sync(0xffffffffu, s, off, 16);
        if (tx == 0) atomicAdd(&g_ksum[b*INNER + ty*8 + j], s);
    }
}

// Pass 2: vsum = Wv @ xsum ; A^T[b][c][o] = w_out[o][c] * ksum*vsum/qsum
// Grid (BATCH, 8): every block computes ss for its b (redundant, cheap),
// writes one 8-o slab of g_At. 64 blocks -> no single-block latency tail.
__global__ void __launch_bounds__(128) k_scale(const float* __restrict__ wqkv,
                                               const float* __restrict__ wout) {
    int b = blockIdx.x, slab = blockIdx.y;   // slab = 8 o's
    int c = threadIdx.x;                     // 128 threads
    __shared__ float ss[INNER];
    __shared__ float xss[DIM];
    if (c < DIM) xss[c] = g_xsum[b*DIM + c];
    __syncthreads();
    // vs = Wv[c,:] . xsum  — per-thread contiguous float4 reads
    float vs = 0.f;
    const float4* wv4 = (const float4*)(wqkv + (size_t)(2*INNER + c)*DIM);
    #pragma unroll
    for (int kk = 0; kk < DIM/4; kk++) {
        float4 w = wv4[kk];
        vs += w.x*xss[4*kk] + w.y*xss[4*kk+1] + w.z*xss[4*kk+2] + w.w*xss[4*kk+3];
    }
    ss[c] = g_ksum[b*INNER + c] * vs / g_qsum[b*INNER + c];
    __syncthreads();
    // write A^T slab: c-major rows, o in [slab*8, slab*8+8)
    for (int idx = c; idx < INNER*8; idx += 128) {
        int cc = idx >> 3, o = slab*8 + (idx & 7);
        g_At[(size_t)b*INNER*64 + cc*64 + o] = wout[o*INNER + cc] * ss[cc];
    }
}

// Pass 3: y[b,o,t] = sum_c A[b,o,c] * E[b,c,t] + b_out[o]
// 256t x 64o tile per block; E streamed in 4 stages of 32c, double-buffered
// via cp.async. Addresses decomposed to base(tid)+immediates to keep regs <128.
__global__ void __launch_bounds__(256, 2) k_out(const float* __restrict__ bout,
                                                float* __restrict__ y) {
    extern __shared__ float sm[];
    float* Es0 = sm;                          // [32][TTO] 32 KB
    float* Es1 = sm + 32*TTO;                 // [32][TTO] 32 KB
    float* As  = sm + 2*32*TTO;               // [128][64] 32 KB (c-major, o inner)
    float* bo  = As + INNER*64;               // [64]
    const int b   = blockIdx.y;
    const int t0  = blockIdx.x * TTO;
    const int tid = threadIdx.x;
    const int tx  = tid & 31;    // t quads at tx*4 and 128+tx*4
    const int ty  = tid >> 5;    // 8 o each -> 64 o

    // Per-thread base pointers; all stage/iter offsets are immediates.
    const float* Ebase = &g_E[(size_t)b*INNER*TLEN + t0];
    const char* psrc = (const char*)Ebase
                     + ((size_t)(tid >> 6)*TLEN + (size_t)(tid & 63)*4)*4;
    const char* asrc = (const char*)&g_At[(size_t)b*INNER*64] + tid*16;
    const uint32_t d0 = smem_u32(Es0) + tid*16;
    const uint32_t d1 = smem_u32(Es1) + tid*16;
    const uint32_t da = smem_u32(As)  + tid*16;

    // group 0: As (32KB) + E stage 0 (32KB)
    #pragma unroll
    for (int i = 0; i < 8; i++) {
        cp16(da + i*4096, asrc + i*4096);
        cp16(d0 + i*4096, psrc + (size_t)(4*i)*TLEN*4);
    }
    CP_COMMIT();
    if (tid < 64) bo[tid] = bout[tid];

    u64 acc[8][4];
    #pragma unroll
    for (int j = 0; j < 8; j++)
        #pragma unroll
        for (int p = 0; p < 4; p++) acc[j][p] = 0ull;

    #pragma unroll
    for (int h = 0; h < 4; h++) {
        if (h < 3) {
            const uint32_t dst = ((h+1) & 1) ? d1 : d0;
            #pragma unroll
            for (int i = 0; i < 8; i++)
                cp16(dst + i*4096, psrc + (size_t)((h+1)*32 + 4*i)*TLEN*4);
            CP_COMMIT();
            CP_WAIT(1);
        } else {
            CP_WAIT(0);
        }
        __syncthreads();   // stage h visible (h=0: also covers As/bo)

        const float* Eb = (h & 1) ? Es1 : Es0;
        const float* Ah = As + h*32*64 + ty*8;
        #pragma unroll 4
        for (int cc = 0; cc < 32; cc++) {
            ulonglong2 ea = *(const ulonglong2*)&Eb[cc*TTO + tx*4];
            ulonglong2 eb = *(const ulonglong2*)&Eb[cc*TTO + 128 + tx*4];
            float4 a0 = *(const float4*)&Ah[cc*64];
            float4 a1 = *(const float4*)&Ah[cc*64 + 4];
            float af[8] = {a0.x,a0.y,a0.z,a0.w,a1.x,a1.y,a1.z,a1.w};
            #pragma unroll
            for (int j = 0; j < 8; j++) {
                u64 ad = pack2(af[j], af[j]);
                fma2(acc[j][0], ad, ea.x);
                fma2(acc[j][1], ad, ea.y);
                fma2(acc[j][2], ad, eb.x);
                fma2(acc[j][3], ad, eb.y);
            }
        }
        __syncthreads();   // reads done before refill of this buffer
    }

    #pragma unroll
    for (int j = 0; j < 8; j++) {
        int o = ty*8 + j;
        u64 bb = pack2(bo[o], bo[o]);
        ulonglong2 r0, r1;
        r0.x = add2(acc[j][0], bb); r0.y = add2(acc[j][1], bb);
        r1.x = add2(acc[j][2], bb); r1.y = add2(acc[j][3], bb);
        float* yb = &y[((size_t)b*64 + o)*TLEN + t0];
        *(ulonglong2*)&yb[tx*4]       = r0;
        *(ulonglong2*)&yb[128 + tx*4] = r1;
    }
}

#define SMEM_REDUCE ((2*DIM*INNER + DIM*TT + 16*TT)*4)   /* 106496 */
#define SMEM_OUT    ((2*32*TTO + INNER*64 + 64)*4)       /*  98560 */

extern "C" void kernel_launch(void* const* d_in, const int* in_sizes, int n_in,
                              void* d_out, int out_size) {
    const float* x    = (const float*)d_in[0];
    const float* wqkv = (const float*)d_in[1];
    const float* wout = (const float*)d_in[2];
    const float* bout = (const float*)d_in[3];
    float* y = (float*)d_out;

    cudaFuncSetAttribute((const void*)k_reduce,
                         cudaFuncAttributeMaxDynamicSharedMemorySize, SMEM_REDUCE);
    cudaFuncSetAttribute((const void*)k_out,
                         cudaFuncAttributeMaxDynamicSharedMemorySize, SMEM_OUT);

    k_setup<<<8, 256>>>(wqkv);
    dim3 g(NTILES, BATCH);
    k_reduce<<<g, 256, SMEM_REDUCE>>>(x);
    dim3 gs(BATCH, 8);
    k_scale<<<gs, 128>>>(wqkv, wout);
    dim3 go(NTILES_O, BATCH);
    k_out<<<go, 256, SMEM_OUT>>>(bout, y);
}